// round 1
// baseline (speedup 1.0000x reference)
#include <cuda_runtime.h>
#include <math.h>

// ---------------------------------------------------------------------------
// CrossTemporalAttention: B=2, C=64, (T,H,W)=(16,48,48), SR=2 -> (8,24,24)
// N = 8*24*24 = 4608 tokens per batch. 4 attention units:
//   unit 0,1 : cross-attn (q from x_down, k/v from xc_down), batch 0/1
//   unit 2,3 : self-attn  (q_sa/k_sa/v_sa from xc_down),     batch 0/1
// ---------------------------------------------------------------------------

#define NPTS 4608          // tokens per batch on downsampled grid
#define TT 8
#define HH 24
#define WW 24

// -------------------- scratch (global device arrays; no allocs) ------------
__device__ float g_xr [2*64*NPTS];     // resized x   [b][c][n]
__device__ float g_xcr[2*64*NPTS];     // resized x_c [b][c][n]
__device__ float g_Q  [4*NPTS*16];     // [unit][n][16]
__device__ float g_K  [4*16*NPTS];     // [unit][c][n]
__device__ float g_V  [4*32*NPTS];     // [unit][c][n]
__device__ float g_O  [4*32*NPTS];     // attention out [unit][c][n]
__device__ float g_Y  [4*64*NPTS];     // up-conv out   [unit][c][n]
__device__ float g_stats[4][2];        // per-unit {mean, rstd}

// -------------------- fast exp (FMA pipe, avoids MUFU bottleneck) ----------
__device__ __forceinline__ float fast_exp(float x) {
    float y = x * 1.442695041f;          // x * log2(e)
    float k = rintf(y);
    float f = y - k;                     // f in [-0.5, 0.5]
    float p = 1.3333558e-3f;
    p = fmaf(p, f, 9.6181291e-3f);
    p = fmaf(p, f, 5.5504109e-2f);
    p = fmaf(p, f, 2.4022651e-1f);
    p = fmaf(p, f, 6.9314718e-1f);
    p = fmaf(p, f, 1.0f);
    return p * __int_as_float(((int)k + 127) << 23);
}

// -------------------- kernel 1: trilinear downsample -----------------------
// thread per (b,c,t,h,w) of downsampled grid; blockIdx.y selects x vs x_c.
__global__ void k_resize(const float* __restrict__ x, const float* __restrict__ xc) {
    int idx = blockIdx.x * 256 + threadIdx.x;
    if (idx >= 2*64*NPTS) return;
    int w = idx % WW;  int tmp = idx / WW;
    int h = tmp % HH;  tmp /= HH;
    int t = tmp % TT;  tmp /= TT;
    int c = tmp % 64;  int b = tmp / 64;

    float pt = (float)t * (15.0f/7.0f);
    int t0 = (int)floorf(pt); t0 = min(max(t0,0),15); int t1 = min(t0+1,15); float wt = pt - (float)t0;
    float ph = (float)h * (47.0f/23.0f);
    int h0 = (int)floorf(ph); h0 = min(max(h0,0),47); int h1 = min(h0+1,47); float wh = ph - (float)h0;
    float pw = (float)w * (47.0f/23.0f);
    int w0 = (int)floorf(pw); w0 = min(max(w0,0),47); int w1 = min(w0+1,47); float ww = pw - (float)w0;

    const float* src = blockIdx.y ? xc : x;
    const float* base = src + ((size_t)(b*64 + c)) * (16*48*48);
    #define VXL(ti,hi,wi) base[((ti)*48 + (hi))*48 + (wi)]
    float a0 = VXL(t0,h0,w0); float a1 = VXL(t0,h0,w1);
    float b0 = VXL(t0,h1,w0); float b1 = VXL(t0,h1,w1);
    float c0 = VXL(t1,h0,w0); float c1 = VXL(t1,h0,w1);
    float d0 = VXL(t1,h1,w0); float d1 = VXL(t1,h1,w1);
    #undef VXL
    float v00 = a0 + (a1-a0)*ww;
    float v01 = b0 + (b1-b0)*ww;
    float v10 = c0 + (c1-c0)*ww;
    float v11 = d0 + (d1-d0)*ww;
    float v0 = v00 + (v01-v00)*wh;
    float v1 = v10 + (v11-v10)*wh;
    float v  = v0  + (v1 - v0)*wt;

    int n = (t*HH + h)*WW + w;
    float* dst = blockIdx.y ? g_xcr : g_xr;
    dst[(b*64 + c)*NPTS + n] = v;
}

// -------------------- kernel 2: down-conv + qkv (x6) + RoPE ----------------
// block = 256 threads handles 8 points (same batch). Stages inputs in smem.
__global__ void __launch_bounds__(256) k_qkv(
    const float* __restrict__ wdn,  const float* __restrict__ bdn,
    const float* __restrict__ wdnc, const float* __restrict__ bdnc,
    const float* __restrict__ wq,   const float* __restrict__ bq,
    const float* __restrict__ wk,   const float* __restrict__ bk,
    const float* __restrict__ wv,   const float* __restrict__ bv,
    const float* __restrict__ wqs,  const float* __restrict__ bqs,
    const float* __restrict__ wks,  const float* __restrict__ bks,
    const float* __restrict__ wvs,  const float* __restrict__ bvs,
    const float* __restrict__ offset, const float* __restrict__ offset_c)
{
    __shared__ float sxr [8][64];
    __shared__ float sxcr[8][64];
    __shared__ float sxd [8][32];
    __shared__ float sxcd[8][32];
    __shared__ float spre[8][64];   // q(0:16) k(16:32) qsa(32:48) ksa(48:64)

    int tid = threadIdx.x;
    int p0  = blockIdx.x * 8;               // global point index in [0, 2*NPTS)
    int b   = p0 / NPTS;                    // constant within block (4608 % 8 == 0)

    // stage 8 points x 64 channels, both tensors
    for (int i = tid; i < 8*64; i += 256) {
        int p = i >> 6, c = i & 63;
        int n = (p0 + p) - b*NPTS;
        sxr [p][c] = g_xr [(b*64 + c)*NPTS + n];
        sxcr[p][c] = g_xcr[(b*64 + c)*NPTS + n];
    }
    __syncthreads();

    // phase A: 64->32 down convs, one (point, oc) per thread
    {
        int p = tid >> 5, oc = tid & 31;
        float a  = bdn[oc];
        float ac = bdnc[oc];
        #pragma unroll
        for (int c = 0; c < 64; c++) {
            a  = fmaf(wdn [oc*64 + c], sxr [p][c], a);
            ac = fmaf(wdnc[oc*64 + c], sxcr[p][c], ac);
        }
        sxd [p][oc] = a;
        sxcd[p][oc] = ac;
    }
    __syncthreads();

    // phase B: q/k/qsa/ksa pre-rope to smem, v/vsa straight to global
    for (int j = 0; j < 4; j++) {
        int item = tid + j*256;             // 1024 items = 8 pts x 128 outputs
        int p = item >> 7, r = item & 127;
        int n = (p0 + p) - b*NPTS;
        if (r < 64) {
            const float* w; const float* bb; const float* src; int o;
            if      (r < 16) { w = wq;  bb = bq;  src = sxd [p]; o = r;      }
            else if (r < 32) { w = wk;  bb = bk;  src = sxcd[p]; o = r - 16; }
            else if (r < 48) { w = wqs; bb = bqs; src = sxcd[p]; o = r - 32; }
            else             { w = wks; bb = bks; src = sxcd[p]; o = r - 48; }
            float acc = bb[o];
            #pragma unroll
            for (int ic = 0; ic < 32; ic++) acc = fmaf(w[o*32 + ic], src[ic], acc);
            spre[p][r] = acc;
        } else {
            const float* w; const float* bb; int o; int unit;
            if (r < 96) { w = wv;  bb = bv;  o = r - 64; unit = b;     }
            else        { w = wvs; bb = bvs; o = r - 96; unit = 2 + b; }
            float acc = bb[o];
            #pragma unroll
            for (int ic = 0; ic < 32; ic++) acc = fmaf(w[o*32 + ic], sxcd[p][ic], acc);
            g_V[(unit*32 + o)*NPTS + n] = acc;
        }
    }
    __syncthreads();

    // phase C: RoPE + scatter to Q/K layouts
    for (int j = 0; j < 2; j++) {
        int item = tid + j*256;             // 512 items = 8 pts x 64 rope outs
        int p = item >> 6, r = item & 63;
        int n  = (p0 + p) - b*NPTS;
        int tt = n / (HH*WW);
        int tensor = r >> 4;                // 0:q 1:k 2:qsa 3:ksa
        int c  = r & 15;
        int cc = c & 7;
        // inv_freq = 10000^(-cc/8) = 2^(-cc * log2(10000)/8)
        float inv = exp2f(-(float)cc * 1.6609640474436812f);
        float ang = (float)tt * inv;
        float sb = sinf(ang), cb = cosf(ang);
        const float* off = (tensor == 1) ? offset_c : offset;
        float o  = off[cc*500 + tt];
        float sv = sb + o, cv = cb + o;
        float x1 = spre[p][tensor*16 + cc];
        float x2 = spre[p][tensor*16 + cc + 8];
        float outv = (c < 8) ? (x1*cv - x2*sv) : (x2*cv + x1*sv);
        if      (tensor == 0) g_Q[(b      *NPTS + n)*16 + c] = outv;
        else if (tensor == 1) g_K[(b*16       + c)*NPTS + n] = outv;
        else if (tensor == 2) g_Q[((2+b)  *NPTS + n)*16 + c] = outv;
        else                  g_K[((2+b)*16   + c)*NPTS + n] = outv;
    }
}

// -------------------- kernel 3: attention (1 query row / thread) -----------
__global__ void __launch_bounds__(128) k_attn() {
    __shared__ float sK[16][64];
    __shared__ float sV[32][64];
    int unit = blockIdx.y;
    int n = blockIdx.x * 128 + threadIdx.x;

    float q[16];
    #pragma unroll
    for (int i = 0; i < 16; i++)
        q[i] = 0.5f * g_Q[(unit*NPTS + n)*16 + i];   // fold 1/SCALE into q
    float acc[32];
    #pragma unroll
    for (int c = 0; c < 32; c++) acc[c] = 0.0f;
    float sum = 0.0f;

    const float* Kb = g_K + unit*16*NPTS;
    const float* Vb = g_V + unit*32*NPTS;

    for (int kb = 0; kb < NPTS; kb += 64) {
        for (int i = threadIdx.x; i < 16*64; i += 128) {
            int c = i >> 6, j2 = i & 63;
            sK[c][j2] = Kb[c*NPTS + kb + j2];
        }
        for (int i = threadIdx.x; i < 32*64; i += 128) {
            int c = i >> 6, j2 = i & 63;
            sV[c][j2] = Vb[c*NPTS + kb + j2];
        }
        __syncthreads();
        #pragma unroll 1
        for (int m = 0; m < 64; m++) {
            float s = 0.0f;
            #pragma unroll
            for (int i = 0; i < 16; i++) s = fmaf(q[i], sK[i][m], s);
            float e = fast_exp(s);          // scores bounded: no max needed
            sum += e;
            #pragma unroll
            for (int c = 0; c < 32; c++) acc[c] = fmaf(e, sV[c][m], acc[c]);
        }
        __syncthreads();
    }
    float rs = 1.0f / sum;
    #pragma unroll
    for (int c = 0; c < 32; c++)
        g_O[(unit*32 + c)*NPTS + n] = acc[c] * rs;
}

// -------------------- kernel 4: groupnorm stats ----------------------------
__global__ void k_gnstats() {
    int unit = blockIdx.x;
    const float* O = g_O + unit*32*NPTS;
    float s = 0.0f, s2 = 0.0f;
    for (int i = threadIdx.x; i < 32*NPTS; i += 256) {
        float v = O[i];
        s += v; s2 = fmaf(v, v, s2);
    }
    __shared__ double sh[256], sh2[256];
    sh[threadIdx.x] = (double)s; sh2[threadIdx.x] = (double)s2;
    __syncthreads();
    for (int st = 128; st > 0; st >>= 1) {
        if (threadIdx.x < st) {
            sh [threadIdx.x] += sh [threadIdx.x + st];
            sh2[threadIdx.x] += sh2[threadIdx.x + st];
        }
        __syncthreads();
    }
    if (threadIdx.x == 0) {
        double inv = 1.0 / (32.0*NPTS);
        double mu  = sh[0] * inv;
        double var = sh2[0] * inv - mu*mu;
        g_stats[unit][0] = (float)mu;
        g_stats[unit][1] = rsqrtf((float)var + 1e-5f);
    }
}

// -------------------- kernel 5: groupnorm + up-conv (32->64) ---------------
__global__ void __launch_bounds__(256) k_convup(
    const float* __restrict__ gnw,  const float* __restrict__ gnb,
    const float* __restrict__ gnws, const float* __restrict__ gnbs,
    const float* __restrict__ wup,  const float* __restrict__ bup,
    const float* __restrict__ wups, const float* __restrict__ bups)
{
    __shared__ float s[32][128];
    __shared__ float sw[64*32];
    __shared__ float sb[64];
    int unit = blockIdx.y;
    int n0 = blockIdx.x * 128;
    const float* gw = (unit < 2) ? gnw  : gnws;
    const float* gb = (unit < 2) ? gnb  : gnbs;
    const float* w  = (unit < 2) ? wup  : wups;
    const float* bb = (unit < 2) ? bup  : bups;
    float mu = g_stats[unit][0], rstd = g_stats[unit][1];

    for (int i = threadIdx.x; i < 64*32; i += 256) sw[i] = w[i];
    if (threadIdx.x < 64) sb[threadIdx.x] = bb[threadIdx.x];
    for (int i = threadIdx.x; i < 32*128; i += 256) {
        int ic = i >> 7, n = i & 127;
        float v = g_O[(unit*32 + ic)*NPTS + n0 + n];
        s[ic][n] = (v - mu)*rstd*gw[ic] + gb[ic];
    }
    __syncthreads();

    int n = threadIdx.x & 127;
    int half = threadIdx.x >> 7;
    float sv[32];
    #pragma unroll
    for (int ic = 0; ic < 32; ic++) sv[ic] = s[ic][n];
    for (int o = half*32; o < half*32 + 32; o++) {
        float a = sb[o];
        #pragma unroll
        for (int ic = 0; ic < 32; ic++) a = fmaf(sw[o*32 + ic], sv[ic], a);
        g_Y[(unit*64 + o)*NPTS + n0 + n] = a;
    }
}

// -------------------- kernel 6: upsample + residual combine ----------------
__global__ void k_final(const float* __restrict__ xc, float* __restrict__ out) {
    int idx = blockIdx.x * 256 + threadIdx.x;
    if (idx >= 2*64*16*48*48) return;
    int W = idx % 48;  int tmp = idx / 48;
    int H = tmp % 48;  tmp /= 48;
    int T = tmp % 16;  tmp /= 16;
    int oc = tmp % 64; int b = tmp / 64;

    float pt = (float)T * (7.0f/15.0f);
    int t0 = min((int)pt, TT-1); int t1 = min(t0+1, TT-1); float wt = pt - (float)t0;
    float ph = (float)H * (23.0f/47.0f);
    int h0 = min((int)ph, HH-1); int h1 = min(h0+1, HH-1); float wh = ph - (float)h0;
    float pw = (float)W * (23.0f/47.0f);
    int w0 = min((int)pw, WW-1); int w1 = min(w0+1, WW-1); float ww = pw - (float)w0;

    const float* Ys = g_Y + ((size_t)((2+b)*64 + oc))*NPTS;
    const float* Yc = g_Y + ((size_t)(b*64 + oc))*NPTS;

    float vs, vc;
    {
        #define TRI(Y, R)                                                          \
        {                                                                          \
            float a0 = Y[(t0*HH + h0)*WW + w0], a1 = Y[(t0*HH + h0)*WW + w1];      \
            float b0 = Y[(t0*HH + h1)*WW + w0], b1 = Y[(t0*HH + h1)*WW + w1];      \
            float c0 = Y[(t1*HH + h0)*WW + w0], c1 = Y[(t1*HH + h0)*WW + w1];      \
            float d0 = Y[(t1*HH + h1)*WW + w0], d1 = Y[(t1*HH + h1)*WW + w1];      \
            float v00 = a0 + (a1-a0)*ww;                                           \
            float v01 = b0 + (b1-b0)*ww;                                           \
            float v10 = c0 + (c1-c0)*ww;                                           \
            float v11 = d0 + (d1-d0)*ww;                                           \
            float v0 = v00 + (v01-v00)*wh;                                         \
            float v1 = v10 + (v11-v10)*wh;                                         \
            R = v0 + (v1-v0)*wt;                                                   \
        }
        TRI(Ys, vs)
        TRI(Yc, vc)
        #undef TRI
    }
    out[idx] = vs + xc[idx] - 0.5f*vc;
}

// ---------------------------------------------------------------------------
extern "C" void kernel_launch(void* const* d_in, const int* in_sizes, int n_in,
                              void* d_out, int out_size) {
    const float* x        = (const float*)d_in[0];
    const float* x_c      = (const float*)d_in[1];
    const float* w_down   = (const float*)d_in[2];
    const float* b_down   = (const float*)d_in[3];
    const float* w_down_c = (const float*)d_in[4];
    const float* b_down_c = (const float*)d_in[5];
    const float* w_q      = (const float*)d_in[6];
    const float* b_q      = (const float*)d_in[7];
    const float* w_k      = (const float*)d_in[8];
    const float* b_k      = (const float*)d_in[9];
    const float* w_v      = (const float*)d_in[10];
    const float* b_v      = (const float*)d_in[11];
    const float* w_q_sa   = (const float*)d_in[12];
    const float* b_q_sa   = (const float*)d_in[13];
    const float* w_k_sa   = (const float*)d_in[14];
    const float* b_k_sa   = (const float*)d_in[15];
    const float* w_v_sa   = (const float*)d_in[16];
    const float* b_v_sa   = (const float*)d_in[17];
    const float* gn_w     = (const float*)d_in[18];
    const float* gn_b     = (const float*)d_in[19];
    const float* gn_w_sa  = (const float*)d_in[20];
    const float* gn_b_sa  = (const float*)d_in[21];
    const float* w_up     = (const float*)d_in[22];
    const float* b_up     = (const float*)d_in[23];
    const float* w_up_sa  = (const float*)d_in[24];
    const float* b_up_sa  = (const float*)d_in[25];
    const float* offset   = (const float*)d_in[26];
    const float* offset_c = (const float*)d_in[27];
    float* out = (float*)d_out;

    // 1) trilinear downsample (both tensors)
    {
        int total = 2*64*NPTS;
        dim3 grid((total + 255)/256, 2);
        k_resize<<<grid, 256>>>(x, x_c);
    }
    // 2) down-conv + q/k/v/q_sa/k_sa/v_sa + rope
    k_qkv<<<2*NPTS/8, 256>>>(w_down, b_down, w_down_c, b_down_c,
                             w_q, b_q, w_k, b_k, w_v, b_v,
                             w_q_sa, b_q_sa, w_k_sa, b_k_sa, w_v_sa, b_v_sa,
                             offset, offset_c);
    // 3) attention (4 units)
    k_attn<<<dim3(NPTS/128, 4), 128>>>();
    // 4) groupnorm statistics
    k_gnstats<<<4, 256>>>();
    // 5) groupnorm + up-conv
    k_convup<<<dim3(NPTS/128, 4), 256>>>(gn_w, gn_b, gn_w_sa, gn_b_sa,
                                         w_up, b_up, w_up_sa, b_up_sa);
    // 6) upsample + residual combine
    k_final<<<(2*64*16*48*48)/256, 256>>>(x_c, out);
}

// round 2
// speedup vs baseline: 1.9504x; 1.9504x over previous
#include <cuda_runtime.h>
#include <math.h>

// ---------------------------------------------------------------------------
// CrossTemporalAttention: B=2, C=64, (T,H,W)=(16,48,48), SR=2 -> (8,24,24)
// N = 4608 tokens/batch. 4 attention units (cross b0/b1, self b0/b1).
// Attention: split-K (4 ways) + packed f32x2 FMA + FMA-pipe exp.
// ---------------------------------------------------------------------------

#define NPTS 4608
#define TT 8
#define HH 24
#define WW 24
#define SPLIT 4
#define MCH (NPTS/SPLIT)   // 1152 keys per split

typedef unsigned long long u64;

// -------------------- scratch (global device arrays; no allocs) ------------
__device__ __align__(16) float g_xr  [2*64*NPTS];
__device__ __align__(16) float g_xcr [2*64*NPTS];
__device__ __align__(16) float g_Q   [4*NPTS*16];      // [unit][n][16]
__device__ __align__(16) float g_K   [4*16*NPTS];      // [unit][c][n]
__device__ __align__(16) float g_V   [4*32*NPTS];      // [unit][c][n]
__device__ __align__(16) float g_pacc[4*SPLIT*32*NPTS];// [unit][split][c][n]
__device__ __align__(16) float g_psum[4*SPLIT*NPTS];
__device__ __align__(16) float g_O   [4*32*NPTS];
__device__ __align__(16) float g_Y   [4*64*NPTS];
__device__ float g_gnpart[4][36][2];
__device__ float g_stats[4][2];

// -------------------- packed f32x2 helpers ---------------------------------
__device__ __forceinline__ u64 fma2(u64 a, u64 b, u64 c) {
    u64 d; asm("fma.rn.f32x2 %0, %1, %2, %3;" : "=l"(d) : "l"(a), "l"(b), "l"(c));
    return d;
}
__device__ __forceinline__ u64 add2(u64 a, u64 b) {
    u64 d; asm("add.rn.f32x2 %0, %1, %2;" : "=l"(d) : "l"(a), "l"(b));
    return d;
}
__device__ __forceinline__ u64 pack2f(float lo, float hi) {
    u64 r; asm("mov.b64 %0, {%1, %2};" : "=l"(r) : "f"(lo), "f"(hi));
    return r;
}
__device__ __forceinline__ void unpack2f(u64 v, float& lo, float& hi) {
    asm("mov.b64 {%0, %1}, %2;" : "=f"(lo), "=f"(hi) : "l"(v));
}

// -------------------- fast exp: all FMA/ALU pipe, no MUFU, no FRND ---------
__device__ __forceinline__ float fexp(float s) {
    const float LOG2E = 1.4426950408889634f;
    const float MAGIC = 12582912.0f;                // 1.5 * 2^23
    float t = fmaf(s, LOG2E, MAGIC);                // round(s*log2e) in low bits
    float k = t - MAGIC;
    float f = fmaf(s, LOG2E, -k);                   // f in [-0.5, 0.5]
    float p = fmaf(9.6181291e-3f, f, 5.5504109e-2f);
    p = fmaf(p, f, 2.4022651e-1f);
    p = fmaf(p, f, 6.9314718e-1f);
    p = fmaf(p, f, 1.0f);
    int sc = (__float_as_int(t) << 23) + 0x3F800000; // (k+127)<<23
    return p * __int_as_float(sc);
}

// -------------------- kernel 1: trilinear downsample -----------------------
__global__ void k_resize(const float* __restrict__ x, const float* __restrict__ xc) {
    int idx = blockIdx.x * 256 + threadIdx.x;
    if (idx >= 2*64*NPTS) return;
    int w = idx % WW;  int tmp = idx / WW;
    int h = tmp % HH;  tmp /= HH;
    int t = tmp % TT;  tmp /= TT;
    int c = tmp % 64;  int b = tmp / 64;

    float pt = (float)t * (15.0f/7.0f);
    int t0 = (int)floorf(pt); t0 = min(max(t0,0),15); int t1 = min(t0+1,15); float wt = pt - (float)t0;
    float ph = (float)h * (47.0f/23.0f);
    int h0 = (int)floorf(ph); h0 = min(max(h0,0),47); int h1 = min(h0+1,47); float wh = ph - (float)h0;
    float pw = (float)w * (47.0f/23.0f);
    int w0 = (int)floorf(pw); w0 = min(max(w0,0),47); int w1 = min(w0+1,47); float ww = pw - (float)w0;

    const float* src = blockIdx.y ? xc : x;
    const float* base = src + ((size_t)(b*64 + c)) * (16*48*48);
    #define VXL(ti,hi,wi) base[((ti)*48 + (hi))*48 + (wi)]
    float a0 = VXL(t0,h0,w0); float a1 = VXL(t0,h0,w1);
    float b0 = VXL(t0,h1,w0); float b1 = VXL(t0,h1,w1);
    float c0 = VXL(t1,h0,w0); float c1 = VXL(t1,h0,w1);
    float d0 = VXL(t1,h1,w0); float d1 = VXL(t1,h1,w1);
    #undef VXL
    float v00 = a0 + (a1-a0)*ww;
    float v01 = b0 + (b1-b0)*ww;
    float v10 = c0 + (c1-c0)*ww;
    float v11 = d0 + (d1-d0)*ww;
    float v0 = v00 + (v01-v00)*wh;
    float v1 = v10 + (v11-v10)*wh;
    float v  = v0  + (v1 - v0)*wt;

    int n = (t*HH + h)*WW + w;
    float* dst = blockIdx.y ? g_xcr : g_xr;
    dst[(b*64 + c)*NPTS + n] = v;
}

// -------------------- kernel 2: down-conv + qkv (x6) + RoPE ----------------
__global__ void __launch_bounds__(256) k_qkv(
    const float* __restrict__ wdn,  const float* __restrict__ bdn,
    const float* __restrict__ wdnc, const float* __restrict__ bdnc,
    const float* __restrict__ wq,   const float* __restrict__ bq,
    const float* __restrict__ wk,   const float* __restrict__ bk,
    const float* __restrict__ wv,   const float* __restrict__ bv,
    const float* __restrict__ wqs,  const float* __restrict__ bqs,
    const float* __restrict__ wks,  const float* __restrict__ bks,
    const float* __restrict__ wvs,  const float* __restrict__ bvs,
    const float* __restrict__ offset, const float* __restrict__ offset_c)
{
    __shared__ float sxr [8][64];
    __shared__ float sxcr[8][64];
    __shared__ float sxd [8][32];
    __shared__ float sxcd[8][32];
    __shared__ float spre[8][64];   // q(0:16) k(16:32) qsa(32:48) ksa(48:64)

    int tid = threadIdx.x;
    int p0  = blockIdx.x * 8;
    int b   = p0 / NPTS;

    for (int i = tid; i < 8*64; i += 256) {
        int p = i >> 6, c = i & 63;
        int n = (p0 + p) - b*NPTS;
        sxr [p][c] = g_xr [(b*64 + c)*NPTS + n];
        sxcr[p][c] = g_xcr[(b*64 + c)*NPTS + n];
    }
    __syncthreads();

    {
        int p = tid >> 5, oc = tid & 31;
        float a  = bdn[oc];
        float ac = bdnc[oc];
        #pragma unroll
        for (int c = 0; c < 64; c++) {
            a  = fmaf(wdn [oc*64 + c], sxr [p][c], a);
            ac = fmaf(wdnc[oc*64 + c], sxcr[p][c], ac);
        }
        sxd [p][oc] = a;
        sxcd[p][oc] = ac;
    }
    __syncthreads();

    for (int j = 0; j < 4; j++) {
        int item = tid + j*256;
        int p = item >> 7, r = item & 127;
        int n = (p0 + p) - b*NPTS;
        if (r < 64) {
            const float* w; const float* bb; const float* src; int o;
            if      (r < 16) { w = wq;  bb = bq;  src = sxd [p]; o = r;      }
            else if (r < 32) { w = wk;  bb = bk;  src = sxcd[p]; o = r - 16; }
            else if (r < 48) { w = wqs; bb = bqs; src = sxcd[p]; o = r - 32; }
            else             { w = wks; bb = bks; src = sxcd[p]; o = r - 48; }
            float acc = bb[o];
            #pragma unroll
            for (int ic = 0; ic < 32; ic++) acc = fmaf(w[o*32 + ic], src[ic], acc);
            spre[p][r] = acc;
        } else {
            const float* w; const float* bb; int o; int unit;
            if (r < 96) { w = wv;  bb = bv;  o = r - 64; unit = b;     }
            else        { w = wvs; bb = bvs; o = r - 96; unit = 2 + b; }
            float acc = bb[o];
            #pragma unroll
            for (int ic = 0; ic < 32; ic++) acc = fmaf(w[o*32 + ic], sxcd[p][ic], acc);
            g_V[(unit*32 + o)*NPTS + n] = acc;
        }
    }
    __syncthreads();

    for (int j = 0; j < 2; j++) {
        int item = tid + j*256;
        int p = item >> 6, r = item & 63;
        int n  = (p0 + p) - b*NPTS;
        int tt = n / (HH*WW);
        int tensor = r >> 4;                // 0:q 1:k 2:qsa 3:ksa
        int c  = r & 15;
        int cc = c & 7;
        float inv = exp2f(-(float)cc * 1.6609640474436812f);
        float ang = (float)tt * inv;
        float sb = sinf(ang), cb = cosf(ang);
        const float* off = (tensor == 1) ? offset_c : offset;
        float o  = off[cc*500 + tt];
        float sv = sb + o, cv = cb + o;
        float x1 = spre[p][tensor*16 + cc];
        float x2 = spre[p][tensor*16 + cc + 8];
        float outv = (c < 8) ? (x1*cv - x2*sv) : (x2*cv + x1*sv);
        if      (tensor == 0) g_Q[(b      *NPTS + n)*16 + c] = outv;
        else if (tensor == 1) g_K[(b*16       + c)*NPTS + n] = outv;
        else if (tensor == 2) g_Q[((2+b)  *NPTS + n)*16 + c] = outv;
        else                  g_K[((2+b)*16   + c)*NPTS + n] = outv;
    }
}

// -------------------- kernel 3: attention, split-K, f32x2 packed -----------
// grid (36, unit=4, split=4), 128 threads; thread = one query row.
__global__ void __launch_bounds__(128) k_attn() {
    __shared__ float sK[16][64];
    __shared__ float sV[32][64];
    int unit  = blockIdx.y;
    int split = blockIdx.z;
    int n = blockIdx.x * 128 + threadIdx.x;

    u64 q2[16];
    {
        const float4* qp = (const float4*)&g_Q[(unit*NPTS + n)*16];
        #pragma unroll
        for (int j = 0; j < 4; j++) {
            float4 v = qp[j];
            q2[4*j+0] = pack2f(0.5f*v.x, 0.5f*v.x);
            q2[4*j+1] = pack2f(0.5f*v.y, 0.5f*v.y);
            q2[4*j+2] = pack2f(0.5f*v.z, 0.5f*v.z);
            q2[4*j+3] = pack2f(0.5f*v.w, 0.5f*v.w);
        }
    }
    u64 acc2[32];
    #pragma unroll
    for (int c = 0; c < 32; c++) acc2[c] = 0ull;
    u64 sum2 = 0ull;

    const float* Kb = g_K + unit*16*NPTS + split*MCH;
    const float* Vb = g_V + unit*32*NPTS + split*MCH;

    for (int kb = 0; kb < MCH; kb += 64) {
        const float* Ksrc = Kb + kb;
        const float* Vsrc = Vb + kb;
        #pragma unroll
        for (int j = 0; j < 2; j++) {
            int idx = threadIdx.x + j*128;
            int r = idx >> 4, c4 = (idx & 15) * 4;
            *(float4*)&sK[r][c4] = *(const float4*)&Ksrc[r*NPTS + c4];
        }
        #pragma unroll
        for (int j = 0; j < 4; j++) {
            int idx = threadIdx.x + j*128;
            int r = idx >> 4, c4 = (idx & 15) * 4;
            *(float4*)&sV[r][c4] = *(const float4*)&Vsrc[r*NPTS + c4];
        }
        __syncthreads();
        #pragma unroll 1
        for (int m = 0; m < 64; m += 4) {
            u64 s01 = 0ull, s23 = 0ull;
            #pragma unroll
            for (int i = 0; i < 16; i++) {
                ulonglong2 kk = *(const ulonglong2*)&sK[i][m];
                s01 = fma2(q2[i], kk.x, s01);
                s23 = fma2(q2[i], kk.y, s23);
            }
            float s0, s1, s2, s3;
            unpack2f(s01, s0, s1);
            unpack2f(s23, s2, s3);
            u64 e01 = pack2f(fexp(s0), fexp(s1));
            u64 e23 = pack2f(fexp(s2), fexp(s3));
            sum2 = add2(sum2, add2(e01, e23));
            #pragma unroll
            for (int c = 0; c < 32; c++) {
                ulonglong2 vv = *(const ulonglong2*)&sV[c][m];
                acc2[c] = fma2(e01, vv.x, acc2[c]);
                acc2[c] = fma2(e23, vv.y, acc2[c]);
            }
        }
        __syncthreads();
    }

    float slo, shi; unpack2f(sum2, slo, shi);
    g_psum[(unit*SPLIT + split)*NPTS + n] = slo + shi;
    float* pa = g_pacc + (size_t)(unit*SPLIT + split)*32*NPTS + n;
    #pragma unroll
    for (int c = 0; c < 32; c++) {
        float lo, hi; unpack2f(acc2[c], lo, hi);
        pa[c*NPTS] = lo + hi;
    }
}

// -------------------- kernel 4: split combine + GN partials ----------------
__global__ void __launch_bounds__(128) k_combine() {
    int unit = blockIdx.y;
    int n = blockIdx.x * 128 + threadIdx.x;
    int tid = threadIdx.x;

    float ssum = 0.0f;
    #pragma unroll
    for (int s = 0; s < SPLIT; s++) ssum += g_psum[(unit*SPLIT + s)*NPTS + n];
    float invs = 1.0f / ssum;

    float bs = 0.0f, bs2 = 0.0f;
    #pragma unroll
    for (int c = 0; c < 32; c++) {
        float a = 0.0f;
        #pragma unroll
        for (int s = 0; s < SPLIT; s++)
            a += g_pacc[((size_t)(unit*SPLIT + s)*32 + c)*NPTS + n];
        float o = a * invs;
        g_O[(unit*32 + c)*NPTS + n] = o;
        bs += o; bs2 = fmaf(o, o, bs2);
    }
    __shared__ float r1[128], r2[128];
    r1[tid] = bs; r2[tid] = bs2;
    __syncthreads();
    for (int st = 64; st > 0; st >>= 1) {
        if (tid < st) { r1[tid] += r1[tid+st]; r2[tid] += r2[tid+st]; }
        __syncthreads();
    }
    if (tid == 0) {
        g_gnpart[unit][blockIdx.x][0] = r1[0];
        g_gnpart[unit][blockIdx.x][1] = r2[0];
    }
}

// -------------------- kernel 5: GN finalize --------------------------------
__global__ void k_gnfinal() {
    int unit = threadIdx.x;
    if (unit < 4) {
        double s = 0.0, s2 = 0.0;
        for (int i = 0; i < 36; i++) {
            s  += (double)g_gnpart[unit][i][0];
            s2 += (double)g_gnpart[unit][i][1];
        }
        double inv = 1.0 / (32.0*NPTS);
        double mu  = s * inv;
        double var = s2 * inv - mu*mu;
        g_stats[unit][0] = (float)mu;
        g_stats[unit][1] = rsqrtf((float)var + 1e-5f);
    }
}

// -------------------- kernel 6: groupnorm + up-conv (32->64) ---------------
__global__ void __launch_bounds__(256) k_convup(
    const float* __restrict__ gnw,  const float* __restrict__ gnb,
    const float* __restrict__ gnws, const float* __restrict__ gnbs,
    const float* __restrict__ wup,  const float* __restrict__ bup,
    const float* __restrict__ wups, const float* __restrict__ bups)
{
    __shared__ float s[32][128];
    __shared__ float sw[64*32];
    __shared__ float sb[64];
    int unit = blockIdx.y;
    int n0 = blockIdx.x * 128;
    const float* gw = (unit < 2) ? gnw  : gnws;
    const float* gb = (unit < 2) ? gnb  : gnbs;
    const float* w  = (unit < 2) ? wup  : wups;
    const float* bb = (unit < 2) ? bup  : bups;
    float mu = g_stats[unit][0], rstd = g_stats[unit][1];

    for (int i = threadIdx.x; i < 64*32; i += 256) sw[i] = w[i];
    if (threadIdx.x < 64) sb[threadIdx.x] = bb[threadIdx.x];
    for (int i = threadIdx.x; i < 32*128; i += 256) {
        int ic = i >> 7, n = i & 127;
        float v = g_O[(unit*32 + ic)*NPTS + n0 + n];
        s[ic][n] = (v - mu)*rstd*gw[ic] + gb[ic];
    }
    __syncthreads();

    int n = threadIdx.x & 127;
    int half = threadIdx.x >> 7;
    float sv[32];
    #pragma unroll
    for (int ic = 0; ic < 32; ic++) sv[ic] = s[ic][n];
    for (int o = half*32; o < half*32 + 32; o++) {
        float a = sb[o];
        #pragma unroll
        for (int ic = 0; ic < 32; ic++) a = fmaf(sw[o*32 + ic], sv[ic], a);
        g_Y[(unit*64 + o)*NPTS + n0 + n] = a;
    }
}

// -------------------- kernel 7: upsample + residual combine ----------------
__global__ void k_final(const float* __restrict__ xc, float* __restrict__ out) {
    int idx = blockIdx.x * 256 + threadIdx.x;
    if (idx >= 2*64*16*48*48) return;
    int W = idx % 48;  int tmp = idx / 48;
    int H = tmp % 48;  tmp /= 48;
    int T = tmp % 16;  tmp /= 16;
    int oc = tmp % 64; int b = tmp / 64;

    float pt = (float)T * (7.0f/15.0f);
    int t0 = min((int)pt, TT-1); int t1 = min(t0+1, TT-1); float wt = pt - (float)t0;
    float ph = (float)H * (23.0f/47.0f);
    int h0 = min((int)ph, HH-1); int h1 = min(h0+1, HH-1); float wh = ph - (float)h0;
    float pw = (float)W * (23.0f/47.0f);
    int w0 = min((int)pw, WW-1); int w1 = min(w0+1, WW-1); float ww = pw - (float)w0;

    const float* Ys = g_Y + ((size_t)((2+b)*64 + oc))*NPTS;
    const float* Yc = g_Y + ((size_t)(b*64 + oc))*NPTS;

    float vs, vc;
    {
        #define TRI(Y, R)                                                          \
        {                                                                          \
            float a0 = Y[(t0*HH + h0)*WW + w0], a1 = Y[(t0*HH + h0)*WW + w1];      \
            float b0 = Y[(t0*HH + h1)*WW + w0], b1 = Y[(t0*HH + h1)*WW + w1];      \
            float c0 = Y[(t1*HH + h0)*WW + w0], c1 = Y[(t1*HH + h0)*WW + w1];      \
            float d0 = Y[(t1*HH + h1)*WW + w0], d1 = Y[(t1*HH + h1)*WW + w1];      \
            float v00 = a0 + (a1-a0)*ww;                                           \
            float v01 = b0 + (b1-b0)*ww;                                           \
            float v10 = c0 + (c1-c0)*ww;                                           \
            float v11 = d0 + (d1-d0)*ww;                                           \
            float v0 = v00 + (v01-v00)*wh;                                         \
            float v1 = v10 + (v11-v10)*wh;                                         \
            R = v0 + (v1-v0)*wt;                                                   \
        }
        TRI(Ys, vs)
        TRI(Yc, vc)
        #undef TRI
    }
    out[idx] = vs + xc[idx] - 0.5f*vc;
}

// ---------------------------------------------------------------------------
extern "C" void kernel_launch(void* const* d_in, const int* in_sizes, int n_in,
                              void* d_out, int out_size) {
    const float* x        = (const float*)d_in[0];
    const float* x_c      = (const float*)d_in[1];
    const float* w_down   = (const float*)d_in[2];
    const float* b_down   = (const float*)d_in[3];
    const float* w_down_c = (const float*)d_in[4];
    const float* b_down_c = (const float*)d_in[5];
    const float* w_q      = (const float*)d_in[6];
    const float* b_q      = (const float*)d_in[7];
    const float* w_k      = (const float*)d_in[8];
    const float* b_k      = (const float*)d_in[9];
    const float* w_v      = (const float*)d_in[10];
    const float* b_v      = (const float*)d_in[11];
    const float* w_q_sa   = (const float*)d_in[12];
    const float* b_q_sa   = (const float*)d_in[13];
    const float* w_k_sa   = (const float*)d_in[14];
    const float* b_k_sa   = (const float*)d_in[15];
    const float* w_v_sa   = (const float*)d_in[16];
    const float* b_v_sa   = (const float*)d_in[17];
    const float* gn_w     = (const float*)d_in[18];
    const float* gn_b     = (const float*)d_in[19];
    const float* gn_w_sa  = (const float*)d_in[20];
    const float* gn_b_sa  = (const float*)d_in[21];
    const float* w_up     = (const float*)d_in[22];
    const float* b_up     = (const float*)d_in[23];
    const float* w_up_sa  = (const float*)d_in[24];
    const float* b_up_sa  = (const float*)d_in[25];
    const float* offset   = (const float*)d_in[26];
    const float* offset_c = (const float*)d_in[27];
    float* out = (float*)d_out;

    {
        int total = 2*64*NPTS;
        dim3 grid((total + 255)/256, 2);
        k_resize<<<grid, 256>>>(x, x_c);
    }
    k_qkv<<<2*NPTS/8, 256>>>(w_down, b_down, w_down_c, b_down_c,
                             w_q, b_q, w_k, b_k, w_v, b_v,
                             w_q_sa, b_q_sa, w_k_sa, b_k_sa, w_v_sa, b_v_sa,
                             offset, offset_c);
    k_attn<<<dim3(NPTS/128, 4, SPLIT), 128>>>();
    k_combine<<<dim3(NPTS/128, 4), 128>>>();
    k_gnfinal<<<1, 4>>>();
    k_convup<<<dim3(NPTS/128, 4), 256>>>(gn_w, gn_b, gn_w_sa, gn_b_sa,
                                         w_up, b_up, w_up_sa, b_up_sa);
    k_final<<<(2*64*16*48*48)/256, 256>>>(x_c, out);
}

// round 3
// speedup vs baseline: 3.7856x; 1.9410x over previous
#include <cuda_runtime.h>
#include <math.h>

// ---------------------------------------------------------------------------
// CrossTemporalAttention: B=2, C=64, (T,H,W)=(16,48,48), SR=2 -> (8,24,24)
// N = 4608 tokens/batch. 4 attention units (cross b0/b1, self b0/b1).
// R3: n-major K/V, QT=2 register blocking, broadcast LDS, double-buffered
//     tiles, transposed smem weights in k_qkv, vectorized combine.
// ---------------------------------------------------------------------------

#define NPTS 4608
#define TT 8
#define HH 24
#define WW 24
#define SPLIT 4
#define MCH (NPTS/SPLIT)   // 1152 keys per split
#define NT (MCH/64)        // 18 tiles of 64 keys

typedef unsigned long long u64;

// -------------------- scratch (global device arrays; no allocs) ------------
__device__ __align__(16) float g_xr  [2*64*NPTS];
__device__ __align__(16) float g_xcr [2*64*NPTS];
__device__ __align__(16) float g_Q   [4*NPTS*16];      // [unit][n][16]
__device__ __align__(16) float g_K   [4*NPTS*16];      // [unit][n][16]  n-major
__device__ __align__(16) float g_V   [4*NPTS*32];      // [unit][n][32]  n-major
__device__ __align__(16) float g_pacc[4*SPLIT*32*NPTS];// [unit][split][c][n]
__device__ __align__(16) float g_psum[4*SPLIT*NPTS];
__device__ __align__(16) float g_O   [4*32*NPTS];      // [unit][c][n]
__device__ __align__(16) float g_Y   [4*64*NPTS];
__device__ float g_gnpart[4][18][2];
__device__ float g_stats[4][2];

// -------------------- packed f32x2 helpers ---------------------------------
__device__ __forceinline__ u64 fma2(u64 a, u64 b, u64 c) {
    u64 d; asm("fma.rn.f32x2 %0, %1, %2, %3;" : "=l"(d) : "l"(a), "l"(b), "l"(c));
    return d;
}
__device__ __forceinline__ u64 pack2f(float lo, float hi) {
    u64 r; asm("mov.b64 %0, {%1, %2};" : "=l"(r) : "f"(lo), "f"(hi));
    return r;
}
__device__ __forceinline__ void unpack2f(u64 v, float& lo, float& hi) {
    asm("mov.b64 {%0, %1}, %2;" : "=f"(lo), "=f"(hi) : "l"(v));
}

// fast exp(s/2): 0.5 folded into log2e. FMA pipe only (no MUFU/FRND).
__device__ __forceinline__ float fexp_half(float s) {
    const float L2EH  = 0.72134752044448170f;       // log2(e)/2
    const float MAGIC = 12582912.0f;                // 1.5 * 2^23
    float t = fmaf(s, L2EH, MAGIC);
    float k = t - MAGIC;
    float f = fmaf(s, L2EH, -k);                    // f in [-0.5, 0.5]
    float p = fmaf(9.6181291e-3f, f, 5.5504109e-2f);
    p = fmaf(p, f, 2.4022651e-1f);
    p = fmaf(p, f, 6.9314718e-1f);
    p = fmaf(p, f, 1.0f);
    int sc = (__float_as_int(t) << 23) + 0x3F800000;
    return p * __int_as_float(sc);
}

// -------------------- kernel 1: trilinear downsample -----------------------
__global__ void k_resize(const float* __restrict__ x, const float* __restrict__ xc) {
    int idx = blockIdx.x * 256 + threadIdx.x;
    if (idx >= 2*64*NPTS) return;
    int w = idx % WW;  int tmp = idx / WW;
    int h = tmp % HH;  tmp /= HH;
    int t = tmp % TT;  tmp /= TT;
    int c = tmp % 64;  int b = tmp / 64;

    float pt = (float)t * (15.0f/7.0f);
    int t0 = (int)floorf(pt); t0 = min(max(t0,0),15); int t1 = min(t0+1,15); float wt = pt - (float)t0;
    float ph = (float)h * (47.0f/23.0f);
    int h0 = (int)floorf(ph); h0 = min(max(h0,0),47); int h1 = min(h0+1,47); float wh = ph - (float)h0;
    float pw = (float)w * (47.0f/23.0f);
    int w0 = (int)floorf(pw); w0 = min(max(w0,0),47); int w1 = min(w0+1,47); float ww = pw - (float)w0;

    const float* src = blockIdx.y ? xc : x;
    const float* base = src + ((size_t)(b*64 + c)) * (16*48*48);
    #define VXL(ti,hi,wi) base[((ti)*48 + (hi))*48 + (wi)]
    float a0 = VXL(t0,h0,w0); float a1 = VXL(t0,h0,w1);
    float b0 = VXL(t0,h1,w0); float b1 = VXL(t0,h1,w1);
    float c0 = VXL(t1,h0,w0); float c1 = VXL(t1,h0,w1);
    float d0 = VXL(t1,h1,w0); float d1 = VXL(t1,h1,w1);
    #undef VXL
    float v00 = a0 + (a1-a0)*ww;
    float v01 = b0 + (b1-b0)*ww;
    float v10 = c0 + (c1-c0)*ww;
    float v11 = d0 + (d1-d0)*ww;
    float v0 = v00 + (v01-v00)*wh;
    float v1 = v10 + (v11-v10)*wh;
    float v  = v0  + (v1 - v0)*wt;

    int n = (t*HH + h)*WW + w;
    float* dst = blockIdx.y ? g_xcr : g_xr;
    dst[(b*64 + c)*NPTS + n] = v;
}

// -------------------- kernel 2: down-conv + qkv (x6) + RoPE ----------------
// block = 256 threads, 8 points. Weights staged TRANSPOSED in smem.
__global__ void __launch_bounds__(256) k_qkv(
    const float* __restrict__ wdn,  const float* __restrict__ bdn,
    const float* __restrict__ wdnc, const float* __restrict__ bdnc,
    const float* __restrict__ wq,   const float* __restrict__ bq,
    const float* __restrict__ wk,   const float* __restrict__ bk,
    const float* __restrict__ wv,   const float* __restrict__ bv,
    const float* __restrict__ wqs,  const float* __restrict__ bqs,
    const float* __restrict__ wks,  const float* __restrict__ bks,
    const float* __restrict__ wvs,  const float* __restrict__ bvs,
    const float* __restrict__ offset, const float* __restrict__ offset_c)
{
    __shared__ float sxr [8][64];
    __shared__ float sxcr[8][64];
    __shared__ float sxd [8][32];
    __shared__ float sxcd[8][32];
    __shared__ float spre[8][64];        // q|k|qsa|ksa pre-rope
    __shared__ float swdT [64][33];      // wdn^T  [c][oc], padded
    __shared__ float swdcT[64][33];      // wdnc^T
    __shared__ float sWB  [32][129];     // phase-B weights^T [ic][o_global]
    __shared__ float sBB  [128];         // phase-B biases

    int tid = threadIdx.x;
    int p0  = blockIdx.x * 8;
    int b   = p0 / NPTS;
    int nb  = p0 - b*NPTS;

    // ---- stage inputs (coalesced: n fastest) ----
    for (int i = tid; i < 8*64; i += 256) {
        int c = i >> 3, p = i & 7;
        sxr [p][c] = g_xr [(b*64 + c)*NPTS + nb + p];
        sxcr[p][c] = g_xcr[(b*64 + c)*NPTS + nb + p];
    }
    // ---- stage down weights transposed (coalesced read, pad-free write) ----
    for (int i = tid; i < 64*32; i += 256) {
        int c = i & 63, oc = i >> 6;
        swdT [c][oc] = wdn [oc*64 + c];
        swdcT[c][oc] = wdnc[oc*64 + c];
    }
    // ---- stage phase-B weights transposed: o 0-15 wq,16-31 wk,32-47 wqs,
    //      48-63 wks, 64-95 wv, 96-127 wvs ----
    for (int i = tid; i < 512; i += 256) {
        int ic = i & 31, o = i >> 5;
        sWB[ic][o]      = wq [o*32 + ic];
        sWB[ic][o + 16] = wk [o*32 + ic];
        sWB[ic][o + 32] = wqs[o*32 + ic];
        sWB[ic][o + 48] = wks[o*32 + ic];
    }
    for (int i = tid; i < 1024; i += 256) {
        int ic = i & 31, o = i >> 5;
        sWB[ic][o + 64] = wv [o*32 + ic];
        sWB[ic][o + 96] = wvs[o*32 + ic];
    }
    if (tid < 128) {
        int o = tid;
        float v;
        if      (o < 16) v = bq [o];
        else if (o < 32) v = bk [o-16];
        else if (o < 48) v = bqs[o-32];
        else if (o < 64) v = bks[o-48];
        else if (o < 96) v = bv [o-64];
        else             v = bvs[o-96];
        sBB[o] = v;
    }
    __syncthreads();

    // ---- phase A: 64->32 down convs (lanes = oc, conflict-free) ----
    {
        int p = tid >> 5, oc = tid & 31;
        float a  = bdn[oc];
        float ac = bdnc[oc];
        #pragma unroll
        for (int c = 0; c < 64; c++) {
            a  = fmaf(swdT [c][oc], sxr [p][c], a);
            ac = fmaf(swdcT[c][oc], sxcr[p][c], ac);
        }
        sxd [p][oc] = a;
        sxcd[p][oc] = ac;
    }
    __syncthreads();

    // ---- phase B: all 6 projections (lanes = o, conflict-free) ----
    #pragma unroll
    for (int j = 0; j < 4; j++) {
        int item = tid + j*256;
        int p = item >> 7, r = item & 127;
        int n = nb + p;
        const float* src = (r < 16) ? sxd[p] : sxcd[p];
        float acc = sBB[r];
        #pragma unroll
        for (int ic = 0; ic < 32; ic++) acc = fmaf(sWB[ic][r], src[ic], acc);
        if (r < 64) {
            spre[p][r] = acc;
        } else if (r < 96) {
            g_V[((size_t)(b*NPTS + n))*32 + (r - 64)] = acc;       // unit b
        } else {
            g_V[((size_t)((2+b)*NPTS + n))*32 + (r - 96)] = acc;   // unit 2+b
        }
    }
    __syncthreads();

    // ---- phase C: RoPE + scatter (Q and K both n-major now) ----
    #pragma unroll
    for (int j = 0; j < 2; j++) {
        int item = tid + j*256;
        int p = item >> 6, r = item & 63;
        int n  = nb + p;
        int tt = n / (HH*WW);
        int tensor = r >> 4;                // 0:q 1:k 2:qsa 3:ksa
        int c  = r & 15;
        int cc = c & 7;
        float inv = exp2f(-(float)cc * 1.6609640474436812f);
        float ang = (float)tt * inv;
        float sb = sinf(ang), cb = cosf(ang);
        const float* off = (tensor == 1) ? offset_c : offset;
        float o  = off[cc*500 + tt];
        float sv = sb + o, cv = cb + o;
        float x1 = spre[p][tensor*16 + cc];
        float x2 = spre[p][tensor*16 + cc + 8];
        float outv = (c < 8) ? (x1*cv - x2*sv) : (x2*cv + x1*sv);
        if      (tensor == 0) g_Q[((size_t)(b*NPTS + n))*16 + c] = outv;
        else if (tensor == 1) g_K[((size_t)(b*NPTS + n))*16 + c] = outv;
        else if (tensor == 2) g_Q[((size_t)((2+b)*NPTS + n))*16 + c] = outv;
        else                  g_K[((size_t)((2+b)*NPTS + n))*16 + c] = outv;
    }
}

// -------------------- kernel 3: attention ----------------------------------
// grid (18, 4 units, SPLIT). 128 threads, 2 queries/thread.
// K/V n-major; all LDS are warp-broadcast. Double-buffered smem tiles.
__global__ void __launch_bounds__(128) k_attn() {
    __shared__ float4 sbuf[2][768];   // per buf: [0:256) K tile, [256:768) V tile
    int unit  = blockIdx.y;
    int split = blockIdx.z;
    int tid = threadIdx.x;
    int n0 = blockIdx.x * 256 + tid * 2;

    // load 2 queries, channel-pair packed (layout already pairs channels)
    u64 q2[2][8];
    {
        const ulonglong2* qp = (const ulonglong2*)&g_Q[((size_t)(unit*NPTS + n0))*16];
        #pragma unroll
        for (int j = 0; j < 4; j++) {
            ulonglong2 a = qp[j];
            q2[0][2*j] = a.x; q2[0][2*j+1] = a.y;
        }
        #pragma unroll
        for (int j = 0; j < 4; j++) {
            ulonglong2 a = qp[4+j];
            q2[1][2*j] = a.x; q2[1][2*j+1] = a.y;
        }
    }
    u64 acc2[2][16];
    #pragma unroll
    for (int j = 0; j < 16; j++) { acc2[0][j] = 0ull; acc2[1][j] = 0ull; }
    float sum0 = 0.0f, sum1 = 0.0f;

    const float4* Kg = (const float4*)(g_K + (size_t)(unit*NPTS + split*MCH)*16);
    const float4* Vg = (const float4*)(g_V + (size_t)(unit*NPTS + split*MCH)*32);

    // preload tile 0
    sbuf[0][tid]       = Kg[tid];
    sbuf[0][tid + 128] = Kg[tid + 128];
    #pragma unroll
    for (int j = 0; j < 4; j++) sbuf[0][256 + tid + 128*j] = Vg[tid + 128*j];
    __syncthreads();

    for (int t = 0; t < NT; t++) {
        float4 pk0, pk1, pv0, pv1, pv2, pv3;
        if (t + 1 < NT) {
            const float4* Kn = Kg + (t+1)*256;
            const float4* Vn = Vg + (t+1)*512;
            pk0 = Kn[tid]; pk1 = Kn[tid + 128];
            pv0 = Vn[tid]; pv1 = Vn[tid + 128];
            pv2 = Vn[tid + 256]; pv3 = Vn[tid + 384];
        }
        const float* buf = (const float*)sbuf[t & 1];
        #pragma unroll 2
        for (int m = 0; m < 64; m++) {
            const ulonglong2* kp = (const ulonglong2*)(buf + m*16);
            u64 s0 = 0ull, s1 = 0ull;
            #pragma unroll
            for (int j = 0; j < 4; j++) {
                ulonglong2 kk = kp[j];
                s0 = fma2(q2[0][2*j],   kk.x, s0);
                s1 = fma2(q2[1][2*j],   kk.x, s1);
                s0 = fma2(q2[0][2*j+1], kk.y, s0);
                s1 = fma2(q2[1][2*j+1], kk.y, s1);
            }
            float a0, b0; unpack2f(s0, a0, b0);
            float a1, b1; unpack2f(s1, a1, b1);
            float e0 = fexp_half(a0 + b0);
            float e1 = fexp_half(a1 + b1);
            sum0 += e0; sum1 += e1;
            u64 e20 = pack2f(e0, e0), e21 = pack2f(e1, e1);
            const ulonglong2* vp = (const ulonglong2*)(buf + 1024 + m*32);
            #pragma unroll
            for (int j = 0; j < 8; j++) {
                ulonglong2 vv = vp[j];
                acc2[0][2*j]   = fma2(e20, vv.x, acc2[0][2*j]);
                acc2[1][2*j]   = fma2(e21, vv.x, acc2[1][2*j]);
                acc2[0][2*j+1] = fma2(e20, vv.y, acc2[0][2*j+1]);
                acc2[1][2*j+1] = fma2(e21, vv.y, acc2[1][2*j+1]);
            }
        }
        __syncthreads();
        if (t + 1 < NT) {
            float4* nb2 = sbuf[(t+1) & 1];
            nb2[tid] = pk0; nb2[tid + 128] = pk1;
            nb2[256 + tid] = pv0;       nb2[256 + tid + 128] = pv1;
            nb2[256 + tid + 256] = pv2; nb2[256 + tid + 384] = pv3;
        }
        __syncthreads();
    }

    // write partials: [unit][split][c][n], coalesced float2 stores
    int us = unit*SPLIT + split;
    *(float2*)&g_psum[(size_t)us*NPTS + n0] = make_float2(sum0, sum1);
    float* pa = g_pacc + (size_t)us*32*NPTS + n0;
    #pragma unroll
    for (int j = 0; j < 16; j++) {
        float lo0, hi0, lo1, hi1;
        unpack2f(acc2[0][j], lo0, hi0);
        unpack2f(acc2[1][j], lo1, hi1);
        *(float2*)&pa[(2*j  )*NPTS] = make_float2(lo0, lo1);
        *(float2*)&pa[(2*j+1)*NPTS] = make_float2(hi0, hi1);
    }
}

// -------------------- kernel 4: split combine + GN partials ----------------
__global__ void __launch_bounds__(128) k_combine() {
    int unit = blockIdx.y;
    int tid = threadIdx.x;
    int n0 = blockIdx.x * 256 + tid * 2;

    float2 ss = make_float2(0.0f, 0.0f);
    #pragma unroll
    for (int s = 0; s < SPLIT; s++) {
        float2 v = *(const float2*)&g_psum[(size_t)(unit*SPLIT + s)*NPTS + n0];
        ss.x += v.x; ss.y += v.y;
    }
    float ix = 1.0f/ss.x, iy = 1.0f/ss.y;

    float bs = 0.0f, bs2 = 0.0f;
    #pragma unroll 4
    for (int c = 0; c < 32; c++) {
        float2 a = make_float2(0.0f, 0.0f);
        #pragma unroll
        for (int s = 0; s < SPLIT; s++) {
            float2 v = *(const float2*)&g_pacc[((size_t)(unit*SPLIT + s)*32 + c)*NPTS + n0];
            a.x += v.x; a.y += v.y;
        }
        float ox = a.x*ix, oy = a.y*iy;
        *(float2*)&g_O[((size_t)(unit*32 + c))*NPTS + n0] = make_float2(ox, oy);
        bs += ox + oy;
        bs2 = fmaf(ox, ox, bs2); bs2 = fmaf(oy, oy, bs2);
    }
    __shared__ float r1[128], r2[128];
    r1[tid] = bs; r2[tid] = bs2;
    __syncthreads();
    for (int st = 64; st > 0; st >>= 1) {
        if (tid < st) { r1[tid] += r1[tid+st]; r2[tid] += r2[tid+st]; }
        __syncthreads();
    }
    if (tid == 0) {
        g_gnpart[unit][blockIdx.x][0] = r1[0];
        g_gnpart[unit][blockIdx.x][1] = r2[0];
    }
}

// -------------------- kernel 5: GN finalize --------------------------------
__global__ void k_gnfinal() {
    int unit = threadIdx.x;
    if (unit < 4) {
        double s = 0.0, s2 = 0.0;
        for (int i = 0; i < 18; i++) {
            s  += (double)g_gnpart[unit][i][0];
            s2 += (double)g_gnpart[unit][i][1];
        }
        double inv = 1.0 / (32.0*NPTS);
        double mu  = s * inv;
        double var = s2 * inv - mu*mu;
        g_stats[unit][0] = (float)mu;
        g_stats[unit][1] = rsqrtf((float)var + 1e-5f);
    }
}

// -------------------- kernel 6: groupnorm + up-conv (32->64) ---------------
__global__ void __launch_bounds__(256) k_convup(
    const float* __restrict__ gnw,  const float* __restrict__ gnb,
    const float* __restrict__ gnws, const float* __restrict__ gnbs,
    const float* __restrict__ wup,  const float* __restrict__ bup,
    const float* __restrict__ wups, const float* __restrict__ bups)
{
    __shared__ float s[32][128];
    __shared__ float sw[64*32];
    __shared__ float sb[64];
    int unit = blockIdx.y;
    int n0 = blockIdx.x * 128;
    const float* gw = (unit < 2) ? gnw  : gnws;
    const float* gb = (unit < 2) ? gnb  : gnbs;
    const float* w  = (unit < 2) ? wup  : wups;
    const float* bb = (unit < 2) ? bup  : bups;
    float mu = g_stats[unit][0], rstd = g_stats[unit][1];

    for (int i = threadIdx.x; i < 64*32; i += 256) sw[i] = w[i];
    if (threadIdx.x < 64) sb[threadIdx.x] = bb[threadIdx.x];
    for (int i = threadIdx.x; i < 32*128; i += 256) {
        int ic = i >> 7, n = i & 127;
        float v = g_O[(unit*32 + ic)*NPTS + n0 + n];
        s[ic][n] = (v - mu)*rstd*gw[ic] + gb[ic];
    }
    __syncthreads();

    int n = threadIdx.x & 127;
    int half = threadIdx.x >> 7;
    float sv[32];
    #pragma unroll
    for (int ic = 0; ic < 32; ic++) sv[ic] = s[ic][n];
    for (int o = half*32; o < half*32 + 32; o++) {
        float a = sb[o];
        #pragma unroll
        for (int ic = 0; ic < 32; ic++) a = fmaf(sw[o*32 + ic], sv[ic], a);
        g_Y[(unit*64 + o)*NPTS + n0 + n] = a;
    }
}

// -------------------- kernel 7: upsample + residual combine ----------------
__global__ void k_final(const float* __restrict__ xc, float* __restrict__ out) {
    int idx = blockIdx.x * 256 + threadIdx.x;
    if (idx >= 2*64*16*48*48) return;
    int W = idx % 48;  int tmp = idx / 48;
    int H = tmp % 48;  tmp /= 48;
    int T = tmp % 16;  tmp /= 16;
    int oc = tmp % 64; int b = tmp / 64;

    float pt = (float)T * (7.0f/15.0f);
    int t0 = min((int)pt, TT-1); int t1 = min(t0+1, TT-1); float wt = pt - (float)t0;
    float ph = (float)H * (23.0f/47.0f);
    int h0 = min((int)ph, HH-1); int h1 = min(h0+1, HH-1); float wh = ph - (float)h0;
    float pw = (float)W * (23.0f/47.0f);
    int w0 = min((int)pw, WW-1); int w1 = min(w0+1, WW-1); float ww = pw - (float)w0;

    const float* Ys = g_Y + ((size_t)((2+b)*64 + oc))*NPTS;
    const float* Yc = g_Y + ((size_t)(b*64 + oc))*NPTS;

    float vs, vc;
    {
        #define TRI(Y, R)                                                          \
        {                                                                          \
            float a0 = Y[(t0*HH + h0)*WW + w0], a1 = Y[(t0*HH + h0)*WW + w1];      \
            float b0 = Y[(t0*HH + h1)*WW + w0], b1 = Y[(t0*HH + h1)*WW + w1];      \
            float c0 = Y[(t1*HH + h0)*WW + w0], c1 = Y[(t1*HH + h0)*WW + w1];      \
            float d0 = Y[(t1*HH + h1)*WW + w0], d1 = Y[(t1*HH + h1)*WW + w1];      \
            float v00 = a0 + (a1-a0)*ww;                                           \
            float v01 = b0 + (b1-b0)*ww;                                           \
            float v10 = c0 + (c1-c0)*ww;                                           \
            float v11 = d0 + (d1-d0)*ww;                                           \
            float v0 = v00 + (v01-v00)*wh;                                         \
            float v1 = v10 + (v11-v10)*wh;                                         \
            R = v0 + (v1-v0)*wt;                                                   \
        }
        TRI(Ys, vs)
        TRI(Yc, vc)
        #undef TRI
    }
    out[idx] = vs + xc[idx] - 0.5f*vc;
}

// ---------------------------------------------------------------------------
extern "C" void kernel_launch(void* const* d_in, const int* in_sizes, int n_in,
                              void* d_out, int out_size) {
    const float* x        = (const float*)d_in[0];
    const float* x_c      = (const float*)d_in[1];
    const float* w_down   = (const float*)d_in[2];
    const float* b_down   = (const float*)d_in[3];
    const float* w_down_c = (const float*)d_in[4];
    const float* b_down_c = (const float*)d_in[5];
    const float* w_q      = (const float*)d_in[6];
    const float* b_q      = (const float*)d_in[7];
    const float* w_k      = (const float*)d_in[8];
    const float* b_k      = (const float*)d_in[9];
    const float* w_v      = (const float*)d_in[10];
    const float* b_v      = (const float*)d_in[11];
    const float* w_q_sa   = (const float*)d_in[12];
    const float* b_q_sa   = (const float*)d_in[13];
    const float* w_k_sa   = (const float*)d_in[14];
    const float* b_k_sa   = (const float*)d_in[15];
    const float* w_v_sa   = (const float*)d_in[16];
    const float* b_v_sa   = (const float*)d_in[17];
    const float* gn_w     = (const float*)d_in[18];
    const float* gn_b     = (const float*)d_in[19];
    const float* gn_w_sa  = (const float*)d_in[20];
    const float* gn_b_sa  = (const float*)d_in[21];
    const float* w_up     = (const float*)d_in[22];
    const float* b_up     = (const float*)d_in[23];
    const float* w_up_sa  = (const float*)d_in[24];
    const float* b_up_sa  = (const float*)d_in[25];
    const float* offset   = (const float*)d_in[26];
    const float* offset_c = (const float*)d_in[27];
    float* out = (float*)d_out;

    {
        int total = 2*64*NPTS;
        dim3 grid((total + 255)/256, 2);
        k_resize<<<grid, 256>>>(x, x_c);
    }
    k_qkv<<<2*NPTS/8, 256>>>(w_down, b_down, w_down_c, b_down_c,
                             w_q, b_q, w_k, b_k, w_v, b_v,
                             w_q_sa, b_q_sa, w_k_sa, b_k_sa, w_v_sa, b_v_sa,
                             offset, offset_c);
    k_attn<<<dim3(NPTS/256, 4, SPLIT), 128>>>();
    k_combine<<<dim3(NPTS/256, 4), 128>>>();
    k_gnfinal<<<1, 4>>>();
    k_convup<<<dim3(NPTS/128, 4), 256>>>(gn_w, gn_b, gn_w_sa, gn_b_sa,
                                         w_up, b_up, w_up_sa, b_up_sa);
    k_final<<<(2*64*16*48*48)/256, 256>>>(x_c, out);
}

// round 5
// speedup vs baseline: 6.3270x; 1.6713x over previous
#include <cuda_runtime.h>
#include <math.h>

// ---------------------------------------------------------------------------
// CrossTemporalAttention: B=2, C=64, (T,H,W)=(16,48,48), SR=2 -> (8,24,24)
// N = 4608 tokens/batch. 4 attention units (cross b0/b1, self b0/b1).
// R5: tensor-core attention (mma.sync m16n8k8 tf32), fused normalize + GN
//     partials in epilogue, k_combine removed. (R4 + cvt.tf32 dest-reg fix.)
// ---------------------------------------------------------------------------

#define NPTS 4608
#define TT 8
#define HH 24
#define WW 24
#define NKT 72            // key tiles of 64

typedef unsigned long long u64;

// -------------------- scratch (global device arrays; no allocs) ------------
__device__ __align__(16) float g_xr  [2*64*NPTS];
__device__ __align__(16) float g_xcr [2*64*NPTS];
__device__ __align__(16) float g_Q   [4*NPTS*16];      // [unit][n][16]
__device__ __align__(16) float g_K   [4*NPTS*16];      // [unit][n][16]
__device__ __align__(16) float g_V   [4*NPTS*32];      // [unit][n][32]
__device__ __align__(16) float g_O   [4*32*NPTS];      // [unit][c][n]
__device__ __align__(16) float g_Y   [4*64*NPTS];
__device__ float g_gnpart[4][NKT][2];
__device__ float g_stats[4][2];

// -------------------- packed f32x2 helpers ---------------------------------
__device__ __forceinline__ u64 fma2(u64 a, u64 b, u64 c) {
    u64 d; asm("fma.rn.f32x2 %0, %1, %2, %3;" : "=l"(d) : "l"(a), "l"(b), "l"(c));
    return d;
}
__device__ __forceinline__ u64 add2(u64 a, u64 b) {
    u64 d; asm("add.rn.f32x2 %0, %1, %2;" : "=l"(d) : "l"(a), "l"(b));
    return d;
}
__device__ __forceinline__ u64 mul2(u64 a, u64 b) {
    u64 d; asm("mul.rn.f32x2 %0, %1, %2;" : "=l"(d) : "l"(a), "l"(b));
    return d;
}
__device__ __forceinline__ u64 pack2f(float lo, float hi) {
    u64 r; asm("mov.b64 %0, {%1, %2};" : "=l"(r) : "f"(lo), "f"(hi));
    return r;
}
__device__ __forceinline__ void unpack2f(u64 v, float& lo, float& hi) {
    asm("mov.b64 {%0, %1}, %2;" : "=f"(lo), "=f"(hi) : "l"(v));
}
// tf32 round: destination must be a b32 register in PTX.
__device__ __forceinline__ float cvt_tf32(float x) {
    unsigned r; asm("cvt.rna.tf32.f32 %0, %1;" : "=r"(r) : "f"(x));
    return __uint_as_float(r);
}

// packed exp on 2 lanes, result truncated to tf32 bits (so the AV mma sees
// EXACTLY the values summed into the softmax denominator).
__device__ __forceinline__ u64 fexp2pair_tf32(u64 s2) {
    const float LOG2E = 1.4426950408889634f;
    const float MAGIC = 12582912.0f;              // 1.5 * 2^23
    u64 l2  = pack2f(LOG2E, LOG2E);
    u64 mg  = pack2f(MAGIC, MAGIC);
    u64 nmg = pack2f(-MAGIC, -MAGIC);
    u64 t2 = fma2(s2, l2, mg);
    u64 k2 = add2(t2, nmg);
    u64 f2 = fma2(s2, l2, k2 ^ 0x8000000080000000ull);
    u64 p = fma2(pack2f(9.6181291e-3f, 9.6181291e-3f), f2,
                 pack2f(5.5504109e-2f, 5.5504109e-2f));
    p = fma2(p, f2, pack2f(2.4022651e-1f, 2.4022651e-1f));
    p = fma2(p, f2, pack2f(6.9314718e-1f, 6.9314718e-1f));
    p = fma2(p, f2, pack2f(1.0f, 1.0f));
    float tlo, thi; unpack2f(t2, tlo, thi);
    int slo = (__float_as_int(tlo) << 23) + 0x3F800000;
    int shi = (__float_as_int(thi) << 23) + 0x3F800000;
    u64 e = mul2(p, pack2f(__int_as_float(slo), __int_as_float(shi)));
    return e & 0xFFFFE000FFFFE000ull;             // tf32 truncation
}

#define MMA_TF32(d, a0, a1, a2, a3, b0, b1)                                     \
    asm volatile(                                                               \
        "mma.sync.aligned.m16n8k8.row.col.f32.tf32.tf32.f32 "                   \
        "{%0,%1,%2,%3},{%4,%5,%6,%7},{%8,%9},{%0,%1,%2,%3};"                    \
        : "+f"(d[0]), "+f"(d[1]), "+f"(d[2]), "+f"(d[3])                        \
        : "r"(a0), "r"(a1), "r"(a2), "r"(a3), "r"(b0), "r"(b1))

// -------------------- kernel 1: trilinear downsample -----------------------
__global__ void k_resize(const float* __restrict__ x, const float* __restrict__ xc) {
    int idx = blockIdx.x * 256 + threadIdx.x;
    if (idx >= 2*64*NPTS) return;
    int w = idx % WW;  int tmp = idx / WW;
    int h = tmp % HH;  tmp /= HH;
    int t = tmp % TT;  tmp /= TT;
    int c = tmp % 64;  int b = tmp / 64;

    float pt = (float)t * (15.0f/7.0f);
    int t0 = (int)floorf(pt); t0 = min(max(t0,0),15); int t1 = min(t0+1,15); float wt = pt - (float)t0;
    float ph = (float)h * (47.0f/23.0f);
    int h0 = (int)floorf(ph); h0 = min(max(h0,0),47); int h1 = min(h0+1,47); float wh = ph - (float)h0;
    float pw = (float)w * (47.0f/23.0f);
    int w0 = (int)floorf(pw); w0 = min(max(w0,0),47); int w1 = min(w0+1,47); float ww = pw - (float)w0;

    const float* src = blockIdx.y ? xc : x;
    const float* base = src + ((size_t)(b*64 + c)) * (16*48*48);
    #define VXL(ti,hi,wi) base[((ti)*48 + (hi))*48 + (wi)]
    float a0 = VXL(t0,h0,w0); float a1 = VXL(t0,h0,w1);
    float b0 = VXL(t0,h1,w0); float b1 = VXL(t0,h1,w1);
    float c0 = VXL(t1,h0,w0); float c1 = VXL(t1,h0,w1);
    float d0 = VXL(t1,h1,w0); float d1 = VXL(t1,h1,w1);
    #undef VXL
    float v00 = a0 + (a1-a0)*ww;
    float v01 = b0 + (b1-b0)*ww;
    float v10 = c0 + (c1-c0)*ww;
    float v11 = d0 + (d1-d0)*ww;
    float v0 = v00 + (v01-v00)*wh;
    float v1 = v10 + (v11-v10)*wh;
    float v  = v0  + (v1 - v0)*wt;

    int n = (t*HH + h)*WW + w;
    float* dst = blockIdx.y ? g_xcr : g_xr;
    dst[(b*64 + c)*NPTS + n] = v;
}

// -------------------- kernel 2: down-conv + qkv (x6) + RoPE ----------------
__global__ void __launch_bounds__(256) k_qkv(
    const float* __restrict__ wdn,  const float* __restrict__ bdn,
    const float* __restrict__ wdnc, const float* __restrict__ bdnc,
    const float* __restrict__ wq,   const float* __restrict__ bq,
    const float* __restrict__ wk,   const float* __restrict__ bk,
    const float* __restrict__ wv,   const float* __restrict__ bv,
    const float* __restrict__ wqs,  const float* __restrict__ bqs,
    const float* __restrict__ wks,  const float* __restrict__ bks,
    const float* __restrict__ wvs,  const float* __restrict__ bvs,
    const float* __restrict__ offset, const float* __restrict__ offset_c)
{
    __shared__ float sxr [8][64];
    __shared__ float sxcr[8][64];
    __shared__ float sxd [8][32];
    __shared__ float sxcd[8][32];
    __shared__ float spre[8][64];
    __shared__ float swdT [64][33];
    __shared__ float swdcT[64][33];
    __shared__ float sWB  [32][129];
    __shared__ float sBB  [128];

    int tid = threadIdx.x;
    int p0  = blockIdx.x * 8;
    int b   = p0 / NPTS;
    int nb  = p0 - b*NPTS;

    for (int i = tid; i < 8*64; i += 256) {
        int c = i >> 3, p = i & 7;
        sxr [p][c] = g_xr [(b*64 + c)*NPTS + nb + p];
        sxcr[p][c] = g_xcr[(b*64 + c)*NPTS + nb + p];
    }
    for (int i = tid; i < 64*32; i += 256) {
        int c = i & 63, oc = i >> 6;
        swdT [c][oc] = wdn [oc*64 + c];
        swdcT[c][oc] = wdnc[oc*64 + c];
    }
    for (int i = tid; i < 512; i += 256) {
        int ic = i & 31, o = i >> 5;
        sWB[ic][o]      = wq [o*32 + ic];
        sWB[ic][o + 16] = wk [o*32 + ic];
        sWB[ic][o + 32] = wqs[o*32 + ic];
        sWB[ic][o + 48] = wks[o*32 + ic];
    }
    for (int i = tid; i < 1024; i += 256) {
        int ic = i & 31, o = i >> 5;
        sWB[ic][o + 64] = wv [o*32 + ic];
        sWB[ic][o + 96] = wvs[o*32 + ic];
    }
    if (tid < 128) {
        int o = tid;
        float v;
        if      (o < 16) v = bq [o];
        else if (o < 32) v = bk [o-16];
        else if (o < 48) v = bqs[o-32];
        else if (o < 64) v = bks[o-48];
        else if (o < 96) v = bv [o-64];
        else             v = bvs[o-96];
        sBB[o] = v;
    }
    __syncthreads();

    {
        int p = tid >> 5, oc = tid & 31;
        float a  = bdn[oc];
        float ac = bdnc[oc];
        #pragma unroll
        for (int c = 0; c < 64; c++) {
            a  = fmaf(swdT [c][oc], sxr [p][c], a);
            ac = fmaf(swdcT[c][oc], sxcr[p][c], ac);
        }
        sxd [p][oc] = a;
        sxcd[p][oc] = ac;
    }
    __syncthreads();

    #pragma unroll
    for (int j = 0; j < 4; j++) {
        int item = tid + j*256;
        int p = item >> 7, r = item & 127;
        int n = nb + p;
        const float* src = (r < 16) ? sxd[p] : sxcd[p];
        float acc = sBB[r];
        #pragma unroll
        for (int ic = 0; ic < 32; ic++) acc = fmaf(sWB[ic][r], src[ic], acc);
        if (r < 64) {
            spre[p][r] = acc;
        } else if (r < 96) {
            g_V[((size_t)(b*NPTS + n))*32 + (r - 64)] = acc;
        } else {
            g_V[((size_t)((2+b)*NPTS + n))*32 + (r - 96)] = acc;
        }
    }
    __syncthreads();

    #pragma unroll
    for (int j = 0; j < 2; j++) {
        int item = tid + j*256;
        int p = item >> 6, r = item & 63;
        int n  = nb + p;
        int tt = n / (HH*WW);
        int tensor = r >> 4;
        int c  = r & 15;
        int cc = c & 7;
        float inv = exp2f(-(float)cc * 1.6609640474436812f);
        float ang = (float)tt * inv;
        float sb = sinf(ang), cb = cosf(ang);
        const float* off = (tensor == 1) ? offset_c : offset;
        float o  = off[cc*500 + tt];
        float sv = sb + o, cv = cb + o;
        float x1 = spre[p][tensor*16 + cc];
        float x2 = spre[p][tensor*16 + cc + 8];
        float outv = (c < 8) ? (x1*cv - x2*sv) : (x2*cv + x1*sv);
        if      (tensor == 0) g_Q[((size_t)(b*NPTS + n))*16 + c] = outv;
        else if (tensor == 1) g_K[((size_t)(b*NPTS + n))*16 + c] = outv;
        else if (tensor == 2) g_Q[((size_t)((2+b)*NPTS + n))*16 + c] = outv;
        else                  g_K[((size_t)((2+b)*NPTS + n))*16 + c] = outv;
    }
}

// -------------------- kernel 3: attention (tensor cores) -------------------
// grid (72 qtiles, 4 units), 128 threads = 4 warps, 16 queries/warp.
__global__ void __launch_bounds__(128) k_attn() {
    __shared__ float sKb[64][20];     // keys x 16 ch, padded (frag loads CF)
    __shared__ float sVb[64][40];     // keys x 32 ch, padded (frag loads CF)
    __shared__ float sP [4][16][68];  // per-warp P tile; reused as sO[32][68]
    __shared__ float sred[2][4];

    int unit = blockIdx.y;
    int qt   = blockIdx.x;
    int tid  = threadIdx.x;
    int w    = tid >> 5;
    int lane = tid & 31;
    int g  = lane >> 2;     // group row 0..7
    int tg = lane & 3;      // thread-in-group 0..3

    // ---- Q fragments (scale 1/SCALE=0.5 folded, tf32-rounded) ----
    unsigned qa[2][4];
    {
        const float* Qg = g_Q + ((size_t)(unit*NPTS + qt*64 + w*16))*16;
        #pragma unroll
        for (int s = 0; s < 2; s++) {
            qa[s][0] = __float_as_uint(cvt_tf32(0.5f*Qg[(g  )*16 + s*8 + tg    ]));
            qa[s][1] = __float_as_uint(cvt_tf32(0.5f*Qg[(g+8)*16 + s*8 + tg    ]));
            qa[s][2] = __float_as_uint(cvt_tf32(0.5f*Qg[(g  )*16 + s*8 + tg + 4]));
            qa[s][3] = __float_as_uint(cvt_tf32(0.5f*Qg[(g+8)*16 + s*8 + tg + 4]));
        }
    }

    float oacc[4][4];
    #pragma unroll
    for (int i = 0; i < 4; i++)
        { oacc[i][0]=0.f; oacc[i][1]=0.f; oacc[i][2]=0.f; oacc[i][3]=0.f; }
    u64 rs2lo = 0ull, rs2hi = 0ull;

    const float4* Kg4 = (const float4*)(g_K + (size_t)unit*NPTS*16);
    const float4* Vg4 = (const float4*)(g_V + (size_t)unit*NPTS*32);

    // ---- stage tile 0 (with tf32 rounding) ----
    #pragma unroll
    for (int j = 0; j < 2; j++) {
        int i = tid + j*128;                 // 256 float4 of K
        float4 v = Kg4[i];
        int key = i >> 2, c4 = (i & 3)*4;
        *(float4*)&sKb[key][c4] = make_float4(cvt_tf32(v.x), cvt_tf32(v.y),
                                              cvt_tf32(v.z), cvt_tf32(v.w));
    }
    #pragma unroll
    for (int j = 0; j < 4; j++) {
        int i = tid + j*128;                 // 512 float4 of V
        float4 v = Vg4[i];
        int key = i >> 3, c4 = (i & 7)*4;
        *(float4*)&sVb[key][c4] = make_float4(cvt_tf32(v.x), cvt_tf32(v.y),
                                              cvt_tf32(v.z), cvt_tf32(v.w));
    }
    __syncthreads();

    float (*pf)[68] = sP[w];

    for (int t = 0; t < NKT; t++) {
        // register prefetch of next tile
        float4 pk0, pk1, pv0, pv1, pv2, pv3;
        if (t + 1 < NKT) {
            const float4* Kn = Kg4 + (size_t)(t+1)*256;
            const float4* Vn = Vg4 + (size_t)(t+1)*512;
            pk0 = Kn[tid]; pk1 = Kn[tid + 128];
            pv0 = Vn[tid]; pv1 = Vn[tid + 128];
            pv2 = Vn[tid + 256]; pv3 = Vn[tid + 384];
        }

        // ---- QK^T : S[16q x 64k] per warp ----
        float sacc[8][4];
        #pragma unroll
        for (int nt = 0; nt < 8; nt++)
            { sacc[nt][0]=0.f; sacc[nt][1]=0.f; sacc[nt][2]=0.f; sacc[nt][3]=0.f; }
        #pragma unroll
        for (int nt = 0; nt < 8; nt++) {
            #pragma unroll
            for (int s = 0; s < 2; s++) {
                unsigned b0 = __float_as_uint(sKb[nt*8 + g][s*8 + tg    ]);
                unsigned b1 = __float_as_uint(sKb[nt*8 + g][s*8 + tg + 4]);
                MMA_TF32(sacc[nt], qa[s][0], qa[s][1], qa[s][2], qa[s][3], b0, b1);
            }
        }
        // ---- exp (packed) + rowsum + stage P ----
        #pragma unroll
        for (int nt = 0; nt < 8; nt++) {
            u64 elo = fexp2pair_tf32(pack2f(sacc[nt][0], sacc[nt][1]));
            u64 ehi = fexp2pair_tf32(pack2f(sacc[nt][2], sacc[nt][3]));
            rs2lo = add2(rs2lo, elo);
            rs2hi = add2(rs2hi, ehi);
            *(u64*)&pf[g    ][nt*8 + 2*tg] = elo;
            *(u64*)&pf[g + 8][nt*8 + 2*tg] = ehi;
        }
        __syncwarp();
        // ---- P @ V : O[16q x 32c] ----
        #pragma unroll
        for (int s = 0; s < 8; s++) {
            unsigned a0 = __float_as_uint(pf[g    ][s*8 + tg    ]);
            unsigned a1 = __float_as_uint(pf[g + 8][s*8 + tg    ]);
            unsigned a2 = __float_as_uint(pf[g    ][s*8 + tg + 4]);
            unsigned a3 = __float_as_uint(pf[g + 8][s*8 + tg + 4]);
            #pragma unroll
            for (int nt = 0; nt < 4; nt++) {
                unsigned b0 = __float_as_uint(sVb[s*8 + tg    ][nt*8 + g]);
                unsigned b1 = __float_as_uint(sVb[s*8 + tg + 4][nt*8 + g]);
                MMA_TF32(oacc[nt], a0, a1, a2, a3, b0, b1);
            }
        }
        __syncthreads();
        if (t + 1 < NKT) {
            {
                int i = tid;
                int key = i >> 2, c4 = (i & 3)*4;
                *(float4*)&sKb[key][c4] = make_float4(cvt_tf32(pk0.x), cvt_tf32(pk0.y),
                                                      cvt_tf32(pk0.z), cvt_tf32(pk0.w));
                i = tid + 128; key = i >> 2; c4 = (i & 3)*4;
                *(float4*)&sKb[key][c4] = make_float4(cvt_tf32(pk1.x), cvt_tf32(pk1.y),
                                                      cvt_tf32(pk1.z), cvt_tf32(pk1.w));
            }
            {
                float4 pv[4] = {pv0, pv1, pv2, pv3};
                #pragma unroll
                for (int j = 0; j < 4; j++) {
                    int i = tid + j*128;
                    int key = i >> 3, c4 = (i & 7)*4;
                    *(float4*)&sVb[key][c4] = make_float4(cvt_tf32(pv[j].x), cvt_tf32(pv[j].y),
                                                          cvt_tf32(pv[j].z), cvt_tf32(pv[j].w));
                }
            }
            __syncthreads();
        }
    }

    // ---- rowsums -> 1/sum per row ----
    float rlo, rhi, r0, r1;
    unpack2f(rs2lo, rlo, rhi); r0 = rlo + rhi;
    unpack2f(rs2hi, rlo, rhi); r1 = rlo + rhi;
    r0 += __shfl_xor_sync(0xFFFFFFFFu, r0, 1);
    r0 += __shfl_xor_sync(0xFFFFFFFFu, r0, 2);
    r1 += __shfl_xor_sync(0xFFFFFFFFu, r1, 1);
    r1 += __shfl_xor_sync(0xFFFFFFFFu, r1, 2);
    float inv0 = 1.0f / r0;
    float inv1 = 1.0f / r1;

    // ---- stage O (transpose to [ch][query]) into sP region ----
    __syncthreads();
    float* sO = &sP[0][0][0];          // [32][68]
    int q = w*16 + g;
    #pragma unroll
    for (int nt = 0; nt < 4; nt++) {
        int ch = nt*8 + 2*tg;
        sO[(ch    )*68 + q    ] = oacc[nt][0]*inv0;
        sO[(ch + 1)*68 + q    ] = oacc[nt][1]*inv0;
        sO[(ch    )*68 + q + 8] = oacc[nt][2]*inv1;
        sO[(ch + 1)*68 + q + 8] = oacc[nt][3]*inv1;
    }
    __syncthreads();

    // ---- coalesced store + GN partials ----
    float s1 = 0.0f, s2 = 0.0f;
    #pragma unroll
    for (int p = 0; p < 4; p++) {
        int lin = tid + p*128;          // 512 float4
        int ch = lin >> 4, f4 = (lin & 15)*4;
        float4 v = *(float4*)&sO[ch*68 + f4];
        *(float4*)&g_O[((size_t)(unit*32 + ch))*NPTS + qt*64 + f4] = v;
        s1 += (v.x + v.y) + (v.z + v.w);
        s2 = fmaf(v.x, v.x, s2); s2 = fmaf(v.y, v.y, s2);
        s2 = fmaf(v.z, v.z, s2); s2 = fmaf(v.w, v.w, s2);
    }
    #pragma unroll
    for (int d = 16; d > 0; d >>= 1) {
        s1 += __shfl_xor_sync(0xFFFFFFFFu, s1, d);
        s2 += __shfl_xor_sync(0xFFFFFFFFu, s2, d);
    }
    if (lane == 0) { sred[0][w] = s1; sred[1][w] = s2; }
    __syncthreads();
    if (tid == 0) {
        g_gnpart[unit][qt][0] = (sred[0][0] + sred[0][1]) + (sred[0][2] + sred[0][3]);
        g_gnpart[unit][qt][1] = (sred[1][0] + sred[1][1]) + (sred[1][2] + sred[1][3]);
    }
}

// -------------------- kernel 4: GN finalize --------------------------------
__global__ void k_gnfinal() {
    int unit = threadIdx.x;
    if (unit < 4) {
        double s = 0.0, s2 = 0.0;
        for (int i = 0; i < NKT; i++) {
            s  += (double)g_gnpart[unit][i][0];
            s2 += (double)g_gnpart[unit][i][1];
        }
        double inv = 1.0 / (32.0*NPTS);
        double mu  = s * inv;
        double var = s2 * inv - mu*mu;
        g_stats[unit][0] = (float)mu;
        g_stats[unit][1] = rsqrtf((float)var + 1e-5f);
    }
}

// -------------------- kernel 5: groupnorm + up-conv (32->64) ---------------
__global__ void __launch_bounds__(256) k_convup(
    const float* __restrict__ gnw,  const float* __restrict__ gnb,
    const float* __restrict__ gnws, const float* __restrict__ gnbs,
    const float* __restrict__ wup,  const float* __restrict__ bup,
    const float* __restrict__ wups, const float* __restrict__ bups)
{
    __shared__ float s[32][128];
    __shared__ float sw[64*32];
    __shared__ float sb[64];
    int unit = blockIdx.y;
    int n0 = blockIdx.x * 128;
    const float* gw = (unit < 2) ? gnw  : gnws;
    const float* gb = (unit < 2) ? gnb  : gnbs;
    const float* w  = (unit < 2) ? wup  : wups;
    const float* bb = (unit < 2) ? bup  : bups;
    float mu = g_stats[unit][0], rstd = g_stats[unit][1];

    for (int i = threadIdx.x; i < 64*32; i += 256) sw[i] = w[i];
    if (threadIdx.x < 64) sb[threadIdx.x] = bb[threadIdx.x];
    for (int i = threadIdx.x; i < 32*128; i += 256) {
        int ic = i >> 7, n = i & 127;
        float v = g_O[(unit*32 + ic)*NPTS + n0 + n];
        s[ic][n] = (v - mu)*rstd*gw[ic] + gb[ic];
    }
    __syncthreads();

    int n = threadIdx.x & 127;
    int half = threadIdx.x >> 7;
    float sv[32];
    #pragma unroll
    for (int ic = 0; ic < 32; ic++) sv[ic] = s[ic][n];
    for (int o = half*32; o < half*32 + 32; o++) {
        float a = sb[o];
        #pragma unroll
        for (int ic = 0; ic < 32; ic++) a = fmaf(sw[o*32 + ic], sv[ic], a);
        g_Y[(unit*64 + o)*NPTS + n0 + n] = a;
    }
}

// -------------------- kernel 6: upsample + residual combine ----------------
__global__ void k_final(const float* __restrict__ xc, float* __restrict__ out) {
    int idx = blockIdx.x * 256 + threadIdx.x;
    if (idx >= 2*64*16*48*48) return;
    int W = idx % 48;  int tmp = idx / 48;
    int H = tmp % 48;  tmp /= 48;
    int T = tmp % 16;  tmp /= 16;
    int oc = tmp % 64; int b = tmp / 64;

    float pt = (float)T * (7.0f/15.0f);
    int t0 = min((int)pt, TT-1); int t1 = min(t0+1, TT-1); float wt = pt - (float)t0;
    float ph = (float)H * (23.0f/47.0f);
    int h0 = min((int)ph, HH-1); int h1 = min(h0+1, HH-1); float wh = ph - (float)h0;
    float pw = (float)W * (23.0f/47.0f);
    int w0 = min((int)pw, WW-1); int w1 = min(w0+1, WW-1); float ww = pw - (float)w0;

    const float* Ys = g_Y + ((size_t)((2+b)*64 + oc))*NPTS;
    const float* Yc = g_Y + ((size_t)(b*64 + oc))*NPTS;

    float vs, vc;
    {
        #define TRI(Y, R)                                                          \
        {                                                                          \
            float a0 = Y[(t0*HH + h0)*WW + w0], a1 = Y[(t0*HH + h0)*WW + w1];      \
            float b0 = Y[(t0*HH + h1)*WW + w0], b1 = Y[(t0*HH + h1)*WW + w1];      \
            float c0 = Y[(t1*HH + h0)*WW + w0], c1 = Y[(t1*HH + h0)*WW + w1];      \
            float d0 = Y[(t1*HH + h1)*WW + w0], d1 = Y[(t1*HH + h1)*WW + w1];      \
            float v00 = a0 + (a1-a0)*ww;                                           \
            float v01 = b0 + (b1-b0)*ww;                                           \
            float v10 = c0 + (c1-c0)*ww;                                           \
            float v11 = d0 + (d1-d0)*ww;                                           \
            float v0 = v00 + (v01-v00)*wh;                                         \
            float v1 = v10 + (v11-v10)*wh;                                         \
            R = v0 + (v1-v0)*wt;                                                   \
        }
        TRI(Ys, vs)
        TRI(Yc, vc)
        #undef TRI
    }
    out[idx] = vs + xc[idx] - 0.5f*vc;
}

// ---------------------------------------------------------------------------
extern "C" void kernel_launch(void* const* d_in, const int* in_sizes, int n_in,
                              void* d_out, int out_size) {
    const float* x        = (const float*)d_in[0];
    const float* x_c      = (const float*)d_in[1];
    const float* w_down   = (const float*)d_in[2];
    const float* b_down   = (const float*)d_in[3];
    const float* w_down_c = (const float*)d_in[4];
    const float* b_down_c = (const float*)d_in[5];
    const float* w_q      = (const float*)d_in[6];
    const float* b_q      = (const float*)d_in[7];
    const float* w_k      = (const float*)d_in[8];
    const float* b_k      = (const float*)d_in[9];
    const float* w_v      = (const float*)d_in[10];
    const float* b_v      = (const float*)d_in[11];
    const float* w_q_sa   = (const float*)d_in[12];
    const float* b_q_sa   = (const float*)d_in[13];
    const float* w_k_sa   = (const float*)d_in[14];
    const float* b_k_sa   = (const float*)d_in[15];
    const float* w_v_sa   = (const float*)d_in[16];
    const float* b_v_sa   = (const float*)d_in[17];
    const float* gn_w     = (const float*)d_in[18];
    const float* gn_b     = (const float*)d_in[19];
    const float* gn_w_sa  = (const float*)d_in[20];
    const float* gn_b_sa  = (const float*)d_in[21];
    const float* w_up     = (const float*)d_in[22];
    const float* b_up     = (const float*)d_in[23];
    const float* w_up_sa  = (const float*)d_in[24];
    const float* b_up_sa  = (const float*)d_in[25];
    const float* offset   = (const float*)d_in[26];
    const float* offset_c = (const float*)d_in[27];
    float* out = (float*)d_out;

    {
        int total = 2*64*NPTS;
        dim3 grid((total + 255)/256, 2);
        k_resize<<<grid, 256>>>(x, x_c);
    }
    k_qkv<<<2*NPTS/8, 256>>>(w_down, b_down, w_down_c, b_down_c,
                             w_q, b_q, w_k, b_k, w_v, b_v,
                             w_q_sa, b_q_sa, w_k_sa, b_k_sa, w_v_sa, b_v_sa,
                             offset, offset_c);
    k_attn<<<dim3(NKT, 4), 128>>>();
    k_gnfinal<<<1, 4>>>();
    k_convup<<<dim3(NPTS/128, 4), 256>>>(gn_w, gn_b, gn_w_sa, gn_b_sa,
                                         w_up, b_up, w_up_sa, b_up_sa);
    k_final<<<(2*64*16*48*48)/256, 256>>>(x_c, out);
}